// round 10
// baseline (speedup 1.0000x reference)
#include <cuda_runtime.h>
#include <math.h>

// DepAttention: B=8, N=256, D=128
//   score[b,i,j] = <val[b,i],val[b,j]> + <dep[b,i,j],dep[b,j,i]>   (symmetric!)
//   out = exp(score/sqrt(D))*adj / (rowsum + 1e-10)
//
// HBM-bound: dep_embed = 268 MB. Symmetric pair enumeration reads each dep
// vector exactly once (vs twice naively).

#define BB   8
#define NN   256
#define DD   128
#define PPB  (NN*(NN+1)/2)     // 32896 unordered pairs (incl. diagonal) per batch
#define PPW  2                 // pairs per warp (MLP)
#define INV_SQRT_D 0.08838834764831845f

__device__ float g_score[BB * NN * NN];   // 2 MB scratch (static __device__: allowed)

// ---------------------------------------------------------------------------
// Kernel A: per-warp dot products over unordered pairs.
// Each lane loads one float4 (16B) of each 128-float vector -> 32 lanes x 4 = 128.
// All loads for PPW pairs issued before any compute (8 independent float4 LDGs).
// ---------------------------------------------------------------------------
__global__ __launch_bounds__(256) void score_kernel(
    const float4* __restrict__ val4,   // [B,N,32] float4
    const float4* __restrict__ dep4)   // [B,N,N,32] float4
{
    const int lane = threadIdx.x & 31;
    const int warp = threadIdx.x >> 5;
    const long long wg = (long long)blockIdx.x * 8 + warp;

    int bi[PPW], ii[PPW], jj[PPW];
    float4 A[PPW], C[PPW], VI[PPW], VJ[PPW];

    // decode pairs + issue all loads
    #pragma unroll
    for (int q = 0; q < PPW; q++) {
        long long p = wg * PPW + q;             // global pair index, exact grid => no bounds check
        int b = (int)(p / PPB);
        int r = (int)(p - (long long)b * PPB);
        // lower-triangle decode: i s.t. i*(i+1)/2 <= r
        int i = (int)((sqrtf(8.0f * (float)r + 1.0f) - 1.0f) * 0.5f);
        while ((i + 1) * (i + 2) / 2 <= r) i++;
        while (i * (i + 1) / 2 > r)       i--;
        int j = r - i * (i + 1) / 2;            // j <= i
        bi[q] = b; ii[q] = i; jj[q] = j;

        long long vij = (((long long)b * NN + i) * NN + j) * (DD / 4) + lane;
        long long vji = (((long long)b * NN + j) * NN + i) * (DD / 4) + lane;
        A[q]  = dep4[vij];
        C[q]  = dep4[vji];
        VI[q] = val4[((long long)b * NN + i) * (DD / 4) + lane];
        VJ[q] = val4[((long long)b * NN + j) * (DD / 4) + lane];
    }

    // dot + warp reduce + symmetric store
    #pragma unroll
    for (int q = 0; q < PPW; q++) {
        float s = A[q].x * C[q].x + A[q].y * C[q].y + A[q].z * C[q].z + A[q].w * C[q].w
                + VI[q].x * VJ[q].x + VI[q].y * VJ[q].y + VI[q].z * VJ[q].z + VI[q].w * VJ[q].w;
        #pragma unroll
        for (int off = 16; off; off >>= 1)
            s += __shfl_xor_sync(0xffffffffu, s, off);
        if (lane == 0) {
            long long base = (long long)bi[q] * NN * NN;
            g_score[base + (long long)ii[q] * NN + jj[q]] = s;
            g_score[base + (long long)jj[q] * NN + ii[q]] = s;
        }
    }
}

// ---------------------------------------------------------------------------
// Kernel B: per-row masked exp-normalize. One block per (b,i), thread j.
// ---------------------------------------------------------------------------
__global__ __launch_bounds__(256) void softmax_kernel(
    const float* __restrict__ adj,
    float* __restrict__ out)
{
    const int  row  = blockIdx.x;            // b*N + i
    const int  j    = threadIdx.x;
    const long long base = (long long)row * NN;

    float s = g_score[base + j] * INV_SQRT_D;
    float e = expf(s) * adj[base + j];

    // block reduce (8 warps)
    __shared__ float red[8];
    float sum = e;
    #pragma unroll
    for (int off = 16; off; off >>= 1)
        sum += __shfl_xor_sync(0xffffffffu, sum, off);
    if ((j & 31) == 0) red[j >> 5] = sum;
    __syncthreads();
    if (j < 32) {
        float v = (j < 8) ? red[j] : 0.0f;
        #pragma unroll
        for (int off = 4; off; off >>= 1)
            v += __shfl_xor_sync(0xffffffffu, v, off);
        if (j == 0) red[0] = v;
    }
    __syncthreads();

    out[base + j] = e / (red[0] + 1e-10f);
}

// ---------------------------------------------------------------------------
extern "C" void kernel_launch(void* const* d_in, const int* in_sizes, int n_in,
                              void* d_out, int out_size)
{
    const float* val = (const float*)d_in[0];   // [8,256,128]
    const float* dep = (const float*)d_in[1];   // [8,256,256,128]
    const float* adj = (const float*)d_in[2];   // [8,256,256]
    float* out = (float*)d_out;                 // [8,256,256]

    // total pairs = 8 * 32896 = 263168; /PPW(2)/8 warps = 16448 blocks (exact)
    score_kernel<<<(BB * PPB) / (PPW * 8), 256>>>((const float4*)val, (const float4*)dep);
    softmax_kernel<<<BB * NN, 256>>>(adj, out);
}

// round 11
// speedup vs baseline: 1.0042x; 1.0042x over previous
#include <cuda_runtime.h>
#include <math.h>

// DepAttention: B=8, N=256, D=128
//   score[b,i,j] = <val[b,i],val[b,j]> + <dep[b,i,j],dep[b,j,i]>   (symmetric!)
//   out = exp(score/sqrt(D))*adj / (rowsum + 1e-10)
//
// HBM-bound: dep_embed = 268 MB. Symmetric pair enumeration reads each dep
// vector exactly once (vs twice naively).

#define BB   8
#define NN   256
#define DD   128
#define PPB  (NN*(NN+1)/2)     // 32896 unordered pairs (incl. diagonal) per batch
#define PPW  2                 // pairs per warp (MLP)
#define INV_SQRT_D 0.08838834764831845f

__device__ float g_score[BB * NN * NN];   // 2 MB scratch (static __device__: allowed)

// ---------------------------------------------------------------------------
// Kernel A: per-warp dot products over unordered pairs.
// Each lane loads one float4 (16B) of each 128-float vector -> 32 lanes x 4 = 128.
// All loads for PPW pairs issued before any compute (8 independent float4 LDGs).
// ---------------------------------------------------------------------------
__global__ __launch_bounds__(256) void score_kernel(
    const float4* __restrict__ val4,   // [B,N,32] float4
    const float4* __restrict__ dep4)   // [B,N,N,32] float4
{
    const int lane = threadIdx.x & 31;
    const int warp = threadIdx.x >> 5;
    const long long wg = (long long)blockIdx.x * 8 + warp;

    int bi[PPW], ii[PPW], jj[PPW];
    float4 A[PPW], C[PPW], VI[PPW], VJ[PPW];

    // decode pairs + issue all loads
    #pragma unroll
    for (int q = 0; q < PPW; q++) {
        long long p = wg * PPW + q;             // global pair index, exact grid => no bounds check
        int b = (int)(p / PPB);
        int r = (int)(p - (long long)b * PPB);
        // lower-triangle decode: i s.t. i*(i+1)/2 <= r
        int i = (int)((sqrtf(8.0f * (float)r + 1.0f) - 1.0f) * 0.5f);
        while ((i + 1) * (i + 2) / 2 <= r) i++;
        while (i * (i + 1) / 2 > r)       i--;
        int j = r - i * (i + 1) / 2;            // j <= i
        bi[q] = b; ii[q] = i; jj[q] = j;

        long long vij = (((long long)b * NN + i) * NN + j) * (DD / 4) + lane;
        long long vji = (((long long)b * NN + j) * NN + i) * (DD / 4) + lane;
        A[q]  = dep4[vij];
        C[q]  = dep4[vji];
        VI[q] = val4[((long long)b * NN + i) * (DD / 4) + lane];
        VJ[q] = val4[((long long)b * NN + j) * (DD / 4) + lane];
    }

    // dot + warp reduce + symmetric store
    #pragma unroll
    for (int q = 0; q < PPW; q++) {
        float s = A[q].x * C[q].x + A[q].y * C[q].y + A[q].z * C[q].z + A[q].w * C[q].w
                + VI[q].x * VJ[q].x + VI[q].y * VJ[q].y + VI[q].z * VJ[q].z + VI[q].w * VJ[q].w;
        #pragma unroll
        for (int off = 16; off; off >>= 1)
            s += __shfl_xor_sync(0xffffffffu, s, off);
        if (lane == 0) {
            long long base = (long long)bi[q] * NN * NN;
            g_score[base + (long long)ii[q] * NN + jj[q]] = s;
            g_score[base + (long long)jj[q] * NN + ii[q]] = s;
        }
    }
}

// ---------------------------------------------------------------------------
// Kernel B: per-row masked exp-normalize. One block per (b,i), thread j.
// ---------------------------------------------------------------------------
__global__ __launch_bounds__(256) void softmax_kernel(
    const float* __restrict__ adj,
    float* __restrict__ out)
{
    const int  row  = blockIdx.x;            // b*N + i
    const int  j    = threadIdx.x;
    const long long base = (long long)row * NN;

    float s = g_score[base + j] * INV_SQRT_D;
    float e = expf(s) * adj[base + j];

    // block reduce (8 warps)
    __shared__ float red[8];
    float sum = e;
    #pragma unroll
    for (int off = 16; off; off >>= 1)
        sum += __shfl_xor_sync(0xffffffffu, sum, off);
    if ((j & 31) == 0) red[j >> 5] = sum;
    __syncthreads();
    if (j < 32) {
        float v = (j < 8) ? red[j] : 0.0f;
        #pragma unroll
        for (int off = 4; off; off >>= 1)
            v += __shfl_xor_sync(0xffffffffu, v, off);
        if (j == 0) red[0] = v;
    }
    __syncthreads();

    out[base + j] = e / (red[0] + 1e-10f);
}

// ---------------------------------------------------------------------------
extern "C" void kernel_launch(void* const* d_in, const int* in_sizes, int n_in,
                              void* d_out, int out_size)
{
    const float* val = (const float*)d_in[0];   // [8,256,128]
    const float* dep = (const float*)d_in[1];   // [8,256,256,128]
    const float* adj = (const float*)d_in[2];   // [8,256,256]
    float* out = (float*)d_out;                 // [8,256,256]

    // total pairs = 8 * 32896 = 263168; /PPW(2)/8 warps = 16448 blocks (exact)
    score_kernel<<<(BB * PPB) / (PPW * 8), 256>>>((const float4*)val, (const float4*)dep);
    softmax_kernel<<<BB * NN, 256>>>(adj, out);
}

// round 12
// speedup vs baseline: 1.0821x; 1.0776x over previous
#include <cuda_runtime.h>
#include <math.h>

// DepAttention: B=8, N=256, D=128
//   score[b,i,j] = <val[b,i],val[b,j]> + <dep[b,i,j],dep[b,j,i]>   (symmetric)
//   out = exp(score/sqrt(D))*adj / (rowsum + 1e-10)
//
// HBM-bound: dep_embed = 268 MB read exactly once via unordered-pair
// enumeration. R11: 5.7 TB/s achieved. This round: __ldcs streaming loads
// (dep is never reused; keep L2 for val/g_score), PPW=4 for deeper MLP,
// cheap incremental pair decode, warp-per-row softmax (no bar.sync).

#define BB   8
#define NN   256
#define DD   128
#define PPB  (NN*(NN+1)/2)     // 32896 unordered pairs per batch
#define PPW  4                 // pairs per warp (PPB % PPW == 0)
#define WPB  8                 // warps per block
#define INV_SQRT_D 0.08838834764831845f

__device__ float g_score[BB * NN * NN];   // 2 MB scratch

// ---------------------------------------------------------------------------
// Kernel A: per-warp dot products over unordered pairs. 16 independent
// LDG.128 issued per lane before any compute. dep loads are streaming
// (__ldcs): 268 MB single-use, don't thrash L2.
// ---------------------------------------------------------------------------
__global__ __launch_bounds__(256) void score_kernel(
    const float4* __restrict__ val4,   // [B,N,32] float4
    const float4* __restrict__ dep4)   // [B,N,N,32] float4
{
    const int lane = threadIdx.x & 31;
    const int warp = threadIdx.x >> 5;
    const int wg   = blockIdx.x * WPB + warp;          // global warp id

    // All PPW pairs of a warp live in the same batch (PPB % PPW == 0).
    const int b = wg / (PPB / PPW);
    int r = (wg - b * (PPB / PPW)) * PPW;              // first pair rank in batch

    // decode first pair of the warp: i s.t. i*(i+1)/2 <= r, j = remainder
    int i = (int)((sqrtf(8.0f * (float)r + 1.0f) - 1.0f) * 0.5f);
    while ((i + 1) * (i + 2) / 2 <= r) i++;
    while (i * (i + 1) / 2 > r)        i--;
    int j = r - i * (i + 1) / 2;                       // j <= i

    const float4* __restrict__ depb = dep4 + (long long)b * (NN * NN * (DD / 4));
    const float4* __restrict__ valb = val4 + b * (NN * (DD / 4));

    float4 A[PPW], C[PPW], VI[PPW], VJ[PPW];
    int is[PPW], js[PPW];

    #pragma unroll
    for (int q = 0; q < PPW; q++) {
        is[q] = i; js[q] = j;
        A[q]  = __ldcs(&depb[(i * NN + j) * (DD / 4) + lane]);
        C[q]  = __ldcs(&depb[(j * NN + i) * (DD / 4) + lane]);
        VI[q] = valb[i * (DD / 4) + lane];
        VJ[q] = valb[j * (DD / 4) + lane];
        // advance to next unordered pair (j-fast within row i)
        j++; if (j > i) { i++; j = 0; }
    }

    const int base = b * NN * NN;
    #pragma unroll
    for (int q = 0; q < PPW; q++) {
        float s = A[q].x * C[q].x + A[q].y * C[q].y + A[q].z * C[q].z + A[q].w * C[q].w
                + VI[q].x * VJ[q].x + VI[q].y * VJ[q].y + VI[q].z * VJ[q].z + VI[q].w * VJ[q].w;
        #pragma unroll
        for (int off = 16; off; off >>= 1)
            s += __shfl_xor_sync(0xffffffffu, s, off);
        if (lane == 0) {
            g_score[base + is[q] * NN + js[q]] = s;    // symmetric write-both
            g_score[base + js[q] * NN + is[q]] = s;    // (diagonal: same addr, same val)
        }
    }
}

// ---------------------------------------------------------------------------
// Kernel B: warp-per-row masked exp-normalize. Each lane owns 8 columns
// (2x float4). Pure shfl reduce — no smem, no __syncthreads.
// ---------------------------------------------------------------------------
__global__ __launch_bounds__(256) void softmax_kernel(
    const float4* __restrict__ adj4,
    float4* __restrict__ out4)
{
    const int lane = threadIdx.x & 31;
    const int warp = threadIdx.x >> 5;
    const int row  = blockIdx.x * WPB + warp;          // b*N + i, 2048 rows
    const int rb   = row * (NN / 4);                   // float4 base

    const float4* sc = ((const float4*)g_score) + rb;
    float4 s0 = sc[lane];
    float4 s1 = sc[lane + 32];
    float4 a0 = adj4[rb + lane];
    float4 a1 = adj4[rb + lane + 32];

    float4 e0, e1;
    e0.x = __expf(s0.x * INV_SQRT_D) * a0.x;
    e0.y = __expf(s0.y * INV_SQRT_D) * a0.y;
    e0.z = __expf(s0.z * INV_SQRT_D) * a0.z;
    e0.w = __expf(s0.w * INV_SQRT_D) * a0.w;
    e1.x = __expf(s1.x * INV_SQRT_D) * a1.x;
    e1.y = __expf(s1.y * INV_SQRT_D) * a1.y;
    e1.z = __expf(s1.z * INV_SQRT_D) * a1.z;
    e1.w = __expf(s1.w * INV_SQRT_D) * a1.w;

    float sum = (e0.x + e0.y) + (e0.z + e0.w) + (e1.x + e1.y) + (e1.z + e1.w);
    #pragma unroll
    for (int off = 16; off; off >>= 1)
        sum += __shfl_xor_sync(0xffffffffu, sum, off);

    float inv = 1.0f / (sum + 1e-10f);
    e0.x *= inv; e0.y *= inv; e0.z *= inv; e0.w *= inv;
    e1.x *= inv; e1.y *= inv; e1.z *= inv; e1.w *= inv;
    out4[rb + lane]      = e0;
    out4[rb + lane + 32] = e1;
}

// ---------------------------------------------------------------------------
extern "C" void kernel_launch(void* const* d_in, const int* in_sizes, int n_in,
                              void* d_out, int out_size)
{
    const float* val = (const float*)d_in[0];   // [8,256,128]
    const float* dep = (const float*)d_in[1];   // [8,256,256,128]
    const float* adj = (const float*)d_in[2];   // [8,256,256]
    float* out = (float*)d_out;                 // [8,256,256]

    // warps = 8*32896/4 = 65792 ; /8 per block = 8224 blocks (exact)
    score_kernel<<<(BB * PPB) / (PPW * WPB), 256>>>((const float4*)val, (const float4*)dep);
    // 2048 rows / 8 warps per block = 256 blocks
    softmax_kernel<<<(BB * NN) / WPB, 256>>>((const float4*)adj, (float4*)out);
}

// round 13
// speedup vs baseline: 1.0877x; 1.0052x over previous
#include <cuda_runtime.h>
#include <math.h>

// DepAttention: B=8, N=256, D=128
//   score[b,i,j] = <val[b,i],val[b,j]> + <dep[b,i,j],dep[b,j,i]>   (symmetric)
//   out = exp(score/sqrt(D))*adj / (rowsum + 1e-10)
//
// HBM-bound: dep_embed = 268 MB read exactly once via unordered-pair
// enumeration. R11: 5.7 TB/s achieved. This round: __ldcs streaming loads
// (dep is never reused; keep L2 for val/g_score), PPW=4 for deeper MLP,
// cheap incremental pair decode, warp-per-row softmax (no bar.sync).

#define BB   8
#define NN   256
#define DD   128
#define PPB  (NN*(NN+1)/2)     // 32896 unordered pairs per batch
#define PPW  4                 // pairs per warp (PPB % PPW == 0)
#define WPB  8                 // warps per block
#define INV_SQRT_D 0.08838834764831845f

__device__ float g_score[BB * NN * NN];   // 2 MB scratch

// ---------------------------------------------------------------------------
// Kernel A: per-warp dot products over unordered pairs. 16 independent
// LDG.128 issued per lane before any compute. dep loads are streaming
// (__ldcs): 268 MB single-use, don't thrash L2.
// ---------------------------------------------------------------------------
__global__ __launch_bounds__(256) void score_kernel(
    const float4* __restrict__ val4,   // [B,N,32] float4
    const float4* __restrict__ dep4)   // [B,N,N,32] float4
{
    const int lane = threadIdx.x & 31;
    const int warp = threadIdx.x >> 5;
    const int wg   = blockIdx.x * WPB + warp;          // global warp id

    // All PPW pairs of a warp live in the same batch (PPB % PPW == 0).
    const int b = wg / (PPB / PPW);
    int r = (wg - b * (PPB / PPW)) * PPW;              // first pair rank in batch

    // decode first pair of the warp: i s.t. i*(i+1)/2 <= r, j = remainder
    int i = (int)((sqrtf(8.0f * (float)r + 1.0f) - 1.0f) * 0.5f);
    while ((i + 1) * (i + 2) / 2 <= r) i++;
    while (i * (i + 1) / 2 > r)        i--;
    int j = r - i * (i + 1) / 2;                       // j <= i

    const float4* __restrict__ depb = dep4 + (long long)b * (NN * NN * (DD / 4));
    const float4* __restrict__ valb = val4 + b * (NN * (DD / 4));

    float4 A[PPW], C[PPW], VI[PPW], VJ[PPW];
    int is[PPW], js[PPW];

    #pragma unroll
    for (int q = 0; q < PPW; q++) {
        is[q] = i; js[q] = j;
        A[q]  = __ldcs(&depb[(i * NN + j) * (DD / 4) + lane]);
        C[q]  = __ldcs(&depb[(j * NN + i) * (DD / 4) + lane]);
        VI[q] = valb[i * (DD / 4) + lane];
        VJ[q] = valb[j * (DD / 4) + lane];
        // advance to next unordered pair (j-fast within row i)
        j++; if (j > i) { i++; j = 0; }
    }

    const int base = b * NN * NN;
    #pragma unroll
    for (int q = 0; q < PPW; q++) {
        float s = A[q].x * C[q].x + A[q].y * C[q].y + A[q].z * C[q].z + A[q].w * C[q].w
                + VI[q].x * VJ[q].x + VI[q].y * VJ[q].y + VI[q].z * VJ[q].z + VI[q].w * VJ[q].w;
        #pragma unroll
        for (int off = 16; off; off >>= 1)
            s += __shfl_xor_sync(0xffffffffu, s, off);
        if (lane == 0) {
            g_score[base + is[q] * NN + js[q]] = s;    // symmetric write-both
            g_score[base + js[q] * NN + is[q]] = s;    // (diagonal: same addr, same val)
        }
    }
}

// ---------------------------------------------------------------------------
// Kernel B: warp-per-row masked exp-normalize. Each lane owns 8 columns
// (2x float4). Pure shfl reduce — no smem, no __syncthreads.
// ---------------------------------------------------------------------------
__global__ __launch_bounds__(256) void softmax_kernel(
    const float4* __restrict__ adj4,
    float4* __restrict__ out4)
{
    const int lane = threadIdx.x & 31;
    const int warp = threadIdx.x >> 5;
    const int row  = blockIdx.x * WPB + warp;          // b*N + i, 2048 rows
    const int rb   = row * (NN / 4);                   // float4 base

    const float4* sc = ((const float4*)g_score) + rb;
    float4 s0 = sc[lane];
    float4 s1 = sc[lane + 32];
    float4 a0 = adj4[rb + lane];
    float4 a1 = adj4[rb + lane + 32];

    float4 e0, e1;
    e0.x = __expf(s0.x * INV_SQRT_D) * a0.x;
    e0.y = __expf(s0.y * INV_SQRT_D) * a0.y;
    e0.z = __expf(s0.z * INV_SQRT_D) * a0.z;
    e0.w = __expf(s0.w * INV_SQRT_D) * a0.w;
    e1.x = __expf(s1.x * INV_SQRT_D) * a1.x;
    e1.y = __expf(s1.y * INV_SQRT_D) * a1.y;
    e1.z = __expf(s1.z * INV_SQRT_D) * a1.z;
    e1.w = __expf(s1.w * INV_SQRT_D) * a1.w;

    float sum = (e0.x + e0.y) + (e0.z + e0.w) + (e1.x + e1.y) + (e1.z + e1.w);
    #pragma unroll
    for (int off = 16; off; off >>= 1)
        sum += __shfl_xor_sync(0xffffffffu, sum, off);

    float inv = 1.0f / (sum + 1e-10f);
    e0.x *= inv; e0.y *= inv; e0.z *= inv; e0.w *= inv;
    e1.x *= inv; e1.y *= inv; e1.z *= inv; e1.w *= inv;
    out4[rb + lane]      = e0;
    out4[rb + lane + 32] = e1;
}

// ---------------------------------------------------------------------------
extern "C" void kernel_launch(void* const* d_in, const int* in_sizes, int n_in,
                              void* d_out, int out_size)
{
    const float* val = (const float*)d_in[0];   // [8,256,128]
    const float* dep = (const float*)d_in[1];   // [8,256,256,128]
    const float* adj = (const float*)d_in[2];   // [8,256,256]
    float* out = (float*)d_out;                 // [8,256,256]

    // warps = 8*32896/4 = 65792 ; /8 per block = 8224 blocks (exact)
    score_kernel<<<(BB * PPB) / (PPW * WPB), 256>>>((const float4*)val, (const float4*)dep);
    // 2048 rows / 8 warps per block = 256 blocks
    softmax_kernel<<<(BB * NN) / WPB, 256>>>((const float4*)adj, (float4*)out);
}